// round 1
// baseline (speedup 1.0000x reference)
#include <cuda_runtime.h>
#include <cstdint>

// ---------------------------------------------------------------------------
// SwinWindowAttention  (B=32, nW=64, W=7 -> N=49, C=128, H=4, hd=32)
// One CTA per window (2048 CTAs, 256 threads). Fully fused:
//   A) QKV = x @ qkv_w + b        (f32x2 packed FMA, smem-staged weights)
//   B) S = (q*scale) @ k^T ; softmax(S + rel_bias + mask)
//   C) O = P @ v                   (f32x2)
//   D) out = O @ proj_w + proj_b   (f32x2)
// ---------------------------------------------------------------------------

#define NW        64
#define NTOK      49
#define CDIM      128
#define HEADS     4
#define HDIM      32
#define SCALE_Q   0.17677669529663687f   // 1/sqrt(32)

#define XS_STRIDE  132   // x / o rows padded (132 mod 32 = 4 -> bank spread)
#define QKV_STRIDE 36    // q/k/v rows padded
#define ATT_STRIDE 53    // attn rows padded (odd -> conflict-free scalar walks)

// shared memory layout (floats).  os aliases xs (xs dead after phase A).
#define SZ_XS   (NTOK * XS_STRIDE)          // 6468
#define SZ_WST  (16 * 384)                  // 6144
#define SZ_QKV1 (HEADS * NTOK * QKV_STRIDE) // 7056
#define SZ_ATT  (HEADS * NTOK * ATT_STRIDE) // 10388
#define SZ_REL  (169 * HEADS)               // 676

#define OFF_XS   0
#define OFF_WST  (OFF_XS  + SZ_XS)
#define OFF_Q    (OFF_WST + SZ_WST)
#define OFF_K    (OFF_Q   + SZ_QKV1)
#define OFF_V    (OFF_K   + SZ_QKV1)
#define OFF_ATT  (OFF_V   + SZ_QKV1)
#define OFF_REL  (OFF_ATT + SZ_ATT)
#define SMEM_FLOATS (OFF_REL + SZ_REL)
#define SMEM_BYTES  (SMEM_FLOATS * 4)

// ---- f32x2 packed-FMA helpers (Blackwell, PTX ISA 8.6) --------------------
__device__ __forceinline__ long long pk2(float v) {
    long long r;
    asm("mov.b64 %0, {%1, %1};" : "=l"(r) : "f"(v));
    return r;
}
__device__ __forceinline__ void fma2(long long& d, long long a, long long b) {
    asm("fma.rn.f32x2 %0, %1, %2, %0;" : "+l"(d) : "l"(a), "l"(b));
}
__device__ __forceinline__ float2 up2(long long a) {
    float2 f;
    asm("mov.b64 {%0, %1}, %2;" : "=f"(f.x), "=f"(f.y) : "l"(a));
    return f;
}
__device__ __forceinline__ long long d2l(double d) { return __double_as_longlong(d); }

__device__ __forceinline__ void store_qkv(float* qs, float* ks, float* vs,
                                          int n, int c, float v) {
    int which = c >> 7;
    int h     = (c >> 5) & 3;
    int d     = c & 31;
    int off   = (h * NTOK + n) * QKV_STRIDE + d;
    if (which == 0)      qs[off] = v * SCALE_Q;
    else if (which == 1) ks[off] = v;
    else                 vs[off] = v;
}

__global__ void __launch_bounds__(256, 1)
swin_window_attention_kernel(const float* __restrict__ xg,
                             const float* __restrict__ maskg,
                             const float* __restrict__ qkvw,
                             const float* __restrict__ qkvb,
                             const float* __restrict__ projw,
                             const float* __restrict__ projb,
                             const float* __restrict__ relg,
                             float* __restrict__ outg)
{
    extern __shared__ float sm[];
    float* xs   = sm + OFF_XS;
    float* wst  = sm + OFF_WST;
    float* qs   = sm + OFF_Q;
    float* ks   = sm + OFF_K;
    float* vs   = sm + OFF_V;
    float* att  = sm + OFF_ATT;
    float* relb = sm + OFF_REL;
    float* os   = xs;              // alias: xs dead after phase A

    const int t    = threadIdx.x;
    const int g    = blockIdx.x;          // window id  (0..2047)
    const int wwin = g & (NW - 1);        // mask index

    // ---- load rel table + x tile ------------------------------------------
    for (int i = t; i < SZ_REL; i += 256) relb[i] = relg[i];
    {
        const float4* xin = reinterpret_cast<const float4*>(xg + (size_t)g * (NTOK * CDIM));
        for (int i = t; i < NTOK * 32; i += 256) {
            int r = i >> 5, c4 = i & 31;
            *reinterpret_cast<float4*>(&xs[r * XS_STRIDE + c4 * 4]) = xin[i];
        }
    }
    __syncthreads();

    // =======================================================================
    // Phase A: QKV GEMM   [49x128] @ [128x384]
    // warp = 7-row group (rt<7 active), lane -> 12 columns (6 f32x2 pairs)
    // =======================================================================
    const int rt   = t >> 5;
    const int lane = t & 31;
    const int c0   = lane * 12;

    long long accA[7][6];
    #pragma unroll
    for (int r = 0; r < 7; r++)
        #pragma unroll
        for (int p = 0; p < 6; p++) accA[r][p] = 0;

    for (int kt = 0; kt < 128; kt += 16) {
        __syncthreads();    // protect wst from previous-iteration readers
        {
            const float4* wg4 = reinterpret_cast<const float4*>(qkvw + kt * 384);
            for (int i = t; i < 16 * 96; i += 256)
                reinterpret_cast<float4*>(wst)[i] = wg4[i];
        }
        __syncthreads();
        if (rt < 7) {
            #pragma unroll 1
            for (int kk4 = 0; kk4 < 16; kk4 += 4) {
                float4 xv[7];
                #pragma unroll
                for (int r = 0; r < 7; r++)
                    xv[r] = *reinterpret_cast<const float4*>(
                        &xs[(rt * 7 + r) * XS_STRIDE + kt + kk4]);
                #pragma unroll
                for (int kk = 0; kk < 4; kk++) {
                    const float* wrow = &wst[(kk4 + kk) * 384 + c0];
                    double2 wab = *reinterpret_cast<const double2*>(wrow);
                    double2 wcd = *reinterpret_cast<const double2*>(wrow + 4);
                    double2 wef = *reinterpret_cast<const double2*>(wrow + 8);
                    long long wb[6] = { d2l(wab.x), d2l(wab.y), d2l(wcd.x),
                                        d2l(wcd.y), d2l(wef.x), d2l(wef.y) };
                    #pragma unroll
                    for (int r = 0; r < 7; r++) {
                        const float* xf = reinterpret_cast<const float*>(&xv[r]);
                        long long xp = pk2(xf[kk]);
                        #pragma unroll
                        for (int p = 0; p < 6; p++) fma2(accA[r][p], xp, wb[p]);
                    }
                }
            }
        }
    }

    // epilogue: + bias, split into q (pre-scaled) / k / v smem
    if (rt < 7) {
        float bq[12];
        #pragma unroll
        for (int p = 0; p < 12; p++) bq[p] = qkvb[c0 + p];
        #pragma unroll
        for (int r = 0; r < 7; r++) {
            int n = rt * 7 + r;
            #pragma unroll
            for (int p = 0; p < 6; p++) {
                float2 f = up2(accA[r][p]);
                int c = c0 + 2 * p;
                store_qkv(qs, ks, vs, n, c,     f.x + bq[2 * p]);
                store_qkv(qs, ks, vs, n, c + 1, f.y + bq[2 * p + 1]);
            }
        }
    }
    __syncthreads();

    // =======================================================================
    // Phase B: S = q @ k^T   (q pre-scaled).  196 threads: (head, 7x7 tile)
    // =======================================================================
    if (t < 196) {
        const int h   = t / 49;
        const int rem = t - h * 49;
        const int ti  = rem / 7;
        const int tj  = rem - ti * 7;
        const float* qb = qs + (h * 49 + ti * 7) * QKV_STRIDE;
        const float* kb = ks + (h * 49 + tj * 7) * QKV_STRIDE;

        float s[7][7];
        #pragma unroll
        for (int r = 0; r < 7; r++)
            #pragma unroll
            for (int c = 0; c < 7; c++) s[r][c] = 0.f;

        #pragma unroll 1
        for (int d4 = 0; d4 < 32; d4 += 4) {
            float4 qv[7], kv[7];
            #pragma unroll
            for (int r = 0; r < 7; r++)
                qv[r] = *reinterpret_cast<const float4*>(&qb[r * QKV_STRIDE + d4]);
            #pragma unroll
            for (int c = 0; c < 7; c++)
                kv[c] = *reinterpret_cast<const float4*>(&kb[c * QKV_STRIDE + d4]);
            #pragma unroll
            for (int r = 0; r < 7; r++)
                #pragma unroll
                for (int c = 0; c < 7; c++) {
                    float acc = s[r][c];
                    acc = fmaf(qv[r].x, kv[c].x, acc);
                    acc = fmaf(qv[r].y, kv[c].y, acc);
                    acc = fmaf(qv[r].z, kv[c].z, acc);
                    acc = fmaf(qv[r].w, kv[c].w, acc);
                    s[r][c] = acc;
                }
        }
        float* ab = att + (h * 49 + ti * 7) * ATT_STRIDE + tj * 7;
        #pragma unroll
        for (int r = 0; r < 7; r++)
            #pragma unroll
            for (int c = 0; c < 7; c++)
                ab[r * ATT_STRIDE + c] = s[r][c];
    }
    __syncthreads();

    // =======================================================================
    // softmax over j, fused with rel-pos bias + shift mask. 196 threads: (h,i)
    // =======================================================================
    if (t < 196) {
        const int h  = t / 49;
        const int i  = t - h * 49;
        const int iy = i / 7, ix = i - iy * 7;
        float* row = att + (h * 49 + i) * ATT_STRIDE;
        const float* mrow = maskg + ((size_t)wwin * 49 + i) * 49;

        float m = -3.0e38f;
        int j = 0;
        for (int jy = 0; jy < 7; jy++) {
            int ry = (iy - jy + 6) * 13;
            for (int jx = 0; jx < 7; jx++, j++) {
                int idx = ry + (ix - jx + 6);
                float v = row[j] + relb[idx * 4 + h] + mrow[j];
                row[j] = v;
                m = fmaxf(m, v);
            }
        }
        float ssum = 0.f;
        for (int j2 = 0; j2 < 49; j2++) {
            float e = __expf(row[j2] - m);
            row[j2] = e;
            ssum += e;
        }
        float inv = 1.0f / ssum;
        for (int j2 = 0; j2 < 49; j2++) row[j2] *= inv;
    }
    __syncthreads();

    // =======================================================================
    // Phase C: O = P @ v.   112 threads: (head, 7-row tile, 8-col tile)
    // =======================================================================
    if (t < 112) {
        const int h   = t / 28;
        const int rem = t - h * 28;
        const int ti  = rem >> 2;
        const int dt  = rem & 3;
        const int i0  = ti * 7, d0 = dt * 8;

        long long accC[7][4];
        #pragma unroll
        for (int r = 0; r < 7; r++)
            #pragma unroll
            for (int p = 0; p < 4; p++) accC[r][p] = 0;

        const float* vb = vs + (h * 49) * QKV_STRIDE + d0;
        const float* pb = att + (h * 49 + i0) * ATT_STRIDE;

        #pragma unroll 1
        for (int j = 0; j < 49; j++) {
            double2 va = *reinterpret_cast<const double2*>(&vb[j * QKV_STRIDE]);
            double2 vc = *reinterpret_cast<const double2*>(&vb[j * QKV_STRIDE + 4]);
            long long v0 = d2l(va.x), v1 = d2l(va.y), v2 = d2l(vc.x), v3 = d2l(vc.y);
            #pragma unroll
            for (int r = 0; r < 7; r++) {
                long long pp = pk2(pb[r * ATT_STRIDE + j]);
                fma2(accC[r][0], pp, v0);
                fma2(accC[r][1], pp, v1);
                fma2(accC[r][2], pp, v2);
                fma2(accC[r][3], pp, v3);
            }
        }
        #pragma unroll
        for (int r = 0; r < 7; r++) {
            float* orow = &os[(i0 + r) * XS_STRIDE + h * HDIM + d0];
            #pragma unroll
            for (int p = 0; p < 4; p++) {
                float2 f = up2(accC[r][p]);
                orow[2 * p]     = f.x;
                orow[2 * p + 1] = f.y;
            }
        }
    }
    __syncthreads();

    // =======================================================================
    // Phase D: out = O @ proj_w + proj_b.  warp = 7-row group, lane -> 4 cols
    // =======================================================================
    long long accD[7][2];
    #pragma unroll
    for (int r = 0; r < 7; r++) { accD[r][0] = 0; accD[r][1] = 0; }
    const int c0d = lane * 4;

    for (int kt = 0; kt < 128; kt += 16) {
        __syncthreads();
        {
            const float4* wg4 = reinterpret_cast<const float4*>(projw + kt * 128);
            for (int i = t; i < 512; i += 256)
                reinterpret_cast<float4*>(wst)[i] = wg4[i];
        }
        __syncthreads();
        if (rt < 7) {
            #pragma unroll 1
            for (int kk4 = 0; kk4 < 16; kk4 += 4) {
                float4 xv[7];
                #pragma unroll
                for (int r = 0; r < 7; r++)
                    xv[r] = *reinterpret_cast<const float4*>(
                        &os[(rt * 7 + r) * XS_STRIDE + kt + kk4]);
                #pragma unroll
                for (int kk = 0; kk < 4; kk++) {
                    double2 wd = *reinterpret_cast<const double2*>(
                        &wst[(kk4 + kk) * 128 + c0d]);
                    long long w0 = d2l(wd.x), w1 = d2l(wd.y);
                    #pragma unroll
                    for (int r = 0; r < 7; r++) {
                        const float* xf = reinterpret_cast<const float*>(&xv[r]);
                        long long xp = pk2(xf[kk]);
                        fma2(accD[r][0], xp, w0);
                        fma2(accD[r][1], xp, w1);
                    }
                }
            }
        }
    }

    if (rt < 7) {
        float4 pb4 = *reinterpret_cast<const float4*>(&projb[c0d]);
        float* ob = outg + (size_t)g * (NTOK * CDIM);
        #pragma unroll
        for (int r = 0; r < 7; r++) {
            int n = rt * 7 + r;
            float2 a = up2(accD[r][0]);
            float2 b = up2(accD[r][1]);
            float4 o4 = make_float4(a.x + pb4.x, a.y + pb4.y,
                                    b.x + pb4.z, b.y + pb4.w);
            *reinterpret_cast<float4*>(&ob[n * CDIM + c0d]) = o4;
        }
    }
}

extern "C" void kernel_launch(void* const* d_in, const int* in_sizes, int n_in,
                              void* d_out, int out_size)
{
    const float* x      = (const float*)d_in[0];
    const float* mask   = (const float*)d_in[1];
    const float* qkv_w  = (const float*)d_in[2];
    const float* qkv_b  = (const float*)d_in[3];
    const float* proj_w = (const float*)d_in[4];
    const float* proj_b = (const float*)d_in[5];
    const float* rel    = (const float*)d_in[6];
    float* out = (float*)d_out;

    cudaFuncSetAttribute(swin_window_attention_kernel,
                         cudaFuncAttributeMaxDynamicSharedMemorySize, SMEM_BYTES);
    swin_window_attention_kernel<<<2048, 256, SMEM_BYTES>>>(
        x, mask, qkv_w, qkv_b, proj_w, proj_b, rel, out);
}

// round 3
// speedup vs baseline: 2.0013x; 2.0013x over previous
#include <cuda_runtime.h>
#include <cuda_bf16.h>
#include <cstdint>

// ===========================================================================
// SwinWindowAttention — HMMA (mma.sync) pipeline (compute_100-safe: no tcgen05)
//   wprep        : qkv_w/proj_w -> transposed bf16 hi/lo
//   gemm_mma<0>  : QKV = x @ qkv_w + b   (bf16 3-pass split, fp32 acc)
//   attn         : per-(window,head) softmax attention (f32x2 SIMT)
//   gemm_mma<1>  : out = O @ proj_w + b
// ===========================================================================

#define SCALE_Q 0.17677669529663687f
#define NWIN    2048
#define TOKENS  100352            // 2048*49
#define MTILES  784               // TOKENS/128
#define ASTRIDE 136               // smem row stride in bf16 (272B: ldmatrix conflict-free)

// ---- device scratch (static: no allocation) -------------------------------
__device__ __nv_bfloat16 g_wqkvT_hi[384 * 128];
__device__ __nv_bfloat16 g_wqkvT_lo[384 * 128];
__device__ __nv_bfloat16 g_wprojT_hi[128 * 128];
__device__ __nv_bfloat16 g_wprojT_lo[128 * 128];
__device__ float g_q[NWIN * 4 * 49 * 32];
__device__ float g_k[NWIN * 4 * 49 * 32];
__device__ float g_v[NWIN * 4 * 49 * 32];
__device__ float g_o[(size_t)TOKENS * 128];

// ---- helpers --------------------------------------------------------------
static __device__ __forceinline__ uint32_t smem_u32(const void* p) {
    uint32_t a;
    asm("{.reg .u64 t; cvta.to.shared.u64 t, %1; cvt.u32.u64 %0, t;}"
        : "=r"(a) : "l"(p));
    return a;
}
static __device__ __forceinline__ long long pk2(float v) {
    long long r; asm("mov.b64 %0, {%1,%1};" : "=l"(r) : "f"(v)); return r;
}
static __device__ __forceinline__ void fma2(long long& d, long long a, long long b) {
    asm("fma.rn.f32x2 %0,%1,%2,%0;" : "+l"(d) : "l"(a), "l"(b));
}
static __device__ __forceinline__ float2 up2(long long a) {
    float2 f; asm("mov.b64 {%0,%1}, %2;" : "=f"(f.x), "=f"(f.y) : "l"(a)); return f;
}
static __device__ __forceinline__ uint32_t pkbf(float a, float b) {
    __nv_bfloat162 t = __floats2bfloat162_rn(a, b);
    return *reinterpret_cast<uint32_t*>(&t);
}
static __device__ __forceinline__ void ldmx4(uint32_t* r, uint32_t a) {
    asm volatile("ldmatrix.sync.aligned.m8n8.x4.shared.b16 {%0,%1,%2,%3}, [%4];"
                 : "=r"(r[0]), "=r"(r[1]), "=r"(r[2]), "=r"(r[3]) : "r"(a));
}
static __device__ __forceinline__ void mma16816(float* d, const uint32_t* a,
                                                const uint32_t* b) {
    asm volatile("mma.sync.aligned.m16n8k16.row.col.f32.bf16.bf16.f32 "
                 "{%0,%1,%2,%3}, {%4,%5,%6,%7}, {%8,%9}, {%0,%1,%2,%3};"
                 : "+f"(d[0]), "+f"(d[1]), "+f"(d[2]), "+f"(d[3])
                 : "r"(a[0]), "r"(a[1]), "r"(a[2]), "r"(a[3]),
                   "r"(b[0]), "r"(b[1]));
}

// ===========================================================================
// Kernel 0: weight prep (transpose + bf16 hi/lo split)
// ===========================================================================
__global__ void wprep(const float* __restrict__ qkvw,
                      const float* __restrict__ projw) {
    int i = blockIdx.x * 256 + threadIdx.x;
    if (i < 384 * 128) {
        int n = i >> 7, k = i & 127;
        float w = qkvw[k * 384 + n];
        __nv_bfloat16 h = __float2bfloat16_rn(w);
        g_wqkvT_hi[i] = h;
        g_wqkvT_lo[i] = __float2bfloat16_rn(w - __bfloat162float(h));
    }
    if (i < 128 * 128) {
        int n = i >> 7, k = i & 127;
        float w = projw[k * 128 + n];
        __nv_bfloat16 h = __float2bfloat16_rn(w);
        g_wprojT_hi[i] = h;
        g_wprojT_lo[i] = __float2bfloat16_rn(w - __bfloat162float(h));
    }
}

// ===========================================================================
// Kernels 1 & 3: bf16-split GEMM via mma.sync m16n8k16
//   CTA: 128x128 out tile, 8 warps (4 row-groups x 2 col-groups, warp=32x64)
//   MODE 0: A = x[TOKENS,128], B = qkv_wT (3 N-chunks), out -> g_q/g_k/g_v
//   MODE 1: A = g_o,           B = proj_wT,             out -> outp + bias
// ===========================================================================
#define SM_GEMM_BYTES (4 * 128 * ASTRIDE * 2)   // Ah, Al, Bh, Bl = 139264 B

template<int MODE>
__global__ void __launch_bounds__(256, 1)
gemm_mma_kernel(const float* __restrict__ Ain,
                const float* __restrict__ bias,
                float* __restrict__ outp)
{
    constexpr int NC = (MODE == 0) ? 3 : 1;
    const __nv_bfloat16* __restrict__ Bhig = (MODE == 0) ? g_wqkvT_hi : g_wprojT_hi;
    const __nv_bfloat16* __restrict__ Blog = (MODE == 0) ? g_wqkvT_lo : g_wprojT_lo;
    const float* __restrict__ A = (MODE == 0) ? Ain : g_o;

    extern __shared__ __nv_bfloat16 smh[];
    __nv_bfloat16* Ah = smh;
    __nv_bfloat16* Al = smh + 128 * ASTRIDE;
    __nv_bfloat16* Bh = smh + 2 * 128 * ASTRIDE;
    __nv_bfloat16* Bl = smh + 3 * 128 * ASTRIDE;

    const int t = threadIdx.x, wid = t >> 5, lane = t & 31;
    const int tile = blockIdx.x;

    // ---- A tile: 128x128 fp32 -> bf16 hi/lo in smem -----------------------
    const float4* a4 = reinterpret_cast<const float4*>(A) + (size_t)tile * 4096;
    #pragma unroll
    for (int it = 0; it < 16; it++) {
        int idx = t + it * 256;                 // 0..4095
        int r = idx >> 5, k = (idx & 31) * 4;
        float4 xv = a4[idx];
        __nv_bfloat16 b0 = __float2bfloat16_rn(xv.x), b1 = __float2bfloat16_rn(xv.y),
                      b2 = __float2bfloat16_rn(xv.z), b3 = __float2bfloat16_rn(xv.w);
        uint2 hi = make_uint2(pkbf(__bfloat162float(b0), __bfloat162float(b1)),
                              pkbf(__bfloat162float(b2), __bfloat162float(b3)));
        uint2 lo = make_uint2(pkbf(xv.x - __bfloat162float(b0), xv.y - __bfloat162float(b1)),
                              pkbf(xv.z - __bfloat162float(b2), xv.w - __bfloat162float(b3)));
        *reinterpret_cast<uint2*>(&Ah[r * ASTRIDE + k]) = hi;
        *reinterpret_cast<uint2*>(&Al[r * ASTRIDE + k]) = lo;
    }
    __syncthreads();

    // warp tiling
    const int wr = wid >> 1, wc = wid & 1;
    const int m0 = wr * 32, n0 = wc * 64;
    // ldmatrix lane addressing
    const int arow = lane & 15,  aco = (lane & 16) ? 8 : 0;
    const int brow = (lane & 7) + ((lane & 16) ? 8 : 0), bco = (lane & 8) ? 8 : 0;
    const int g = lane >> 2, tig2 = (lane & 3) * 2;

    for (int nc = 0; nc < NC; nc++) {
        // ---- B chunk: 128 rows (N) x 128 (K) bf16 hi/lo -------------------
        const uint4* bh4 = reinterpret_cast<const uint4*>(Bhig + nc * 16384);
        const uint4* bl4 = reinterpret_cast<const uint4*>(Blog + nc * 16384);
        #pragma unroll
        for (int it = 0; it < 8; it++) {
            int idx = t + it * 256;             // 0..2047, uint4 = 8 bf16
            int j = idx >> 4, k0 = (idx & 15) * 8;
            *reinterpret_cast<uint4*>(&Bh[j * ASTRIDE + k0]) = bh4[idx];
            *reinterpret_cast<uint4*>(&Bl[j * ASTRIDE + k0]) = bl4[idx];
        }
        __syncthreads();

        float acc[2][8][4];
        #pragma unroll
        for (int tm = 0; tm < 2; tm++)
            #pragma unroll
            for (int tn = 0; tn < 8; tn++)
                #pragma unroll
                for (int e = 0; e < 4; e++) acc[tm][tn][e] = 0.f;

        #pragma unroll
        for (int pass = 0; pass < 3; pass++) {      // hh, hl, lh
            const __nv_bfloat16* Ap = (pass == 2) ? Al : Ah;
            const __nv_bfloat16* Bp = (pass == 1) ? Bl : Bh;
            const uint32_t abase = smem_u32(Ap + (m0 + arow) * ASTRIDE + aco);
            const uint32_t bbase = smem_u32(Bp + (n0 + brow) * ASTRIDE + bco);
            #pragma unroll
            for (int ks = 0; ks < 8; ks++) {        // k16 steps
                const uint32_t koff = (uint32_t)(ks * 16 * 2);
                uint32_t af[2][4], bf[4][4];
                ldmx4(af[0], abase + koff);
                ldmx4(af[1], abase + 16 * ASTRIDE * 2 + koff);
                #pragma unroll
                for (int tb = 0; tb < 4; tb++)
                    ldmx4(bf[tb], bbase + tb * 16 * ASTRIDE * 2 + koff);
                #pragma unroll
                for (int tm = 0; tm < 2; tm++)
                    #pragma unroll
                    for (int tn = 0; tn < 8; tn++)
                        mma16816(acc[tm][tn], af[tm], &bf[tn >> 1][(tn & 1) * 2]);
            }
        }

        // ---- epilogue: regs -> gmem ---------------------------------------
        #pragma unroll
        for (int tm = 0; tm < 2; tm++) {
            #pragma unroll
            for (int tn = 0; tn < 8; tn++) {
                const int col = n0 + tn * 8 + tig2;
                float2 b2v = __ldg(reinterpret_cast<const float2*>(
                                   bias + (MODE == 0 ? nc * 128 : 0) + col));
                #pragma unroll
                for (int hh = 0; hh < 2; hh++) {
                    const int m = m0 + tm * 16 + g + hh * 8;
                    const int token = tile * 128 + m;
                    float vx = acc[tm][tn][hh * 2 + 0] + b2v.x;
                    float vy = acc[tm][tn][hh * 2 + 1] + b2v.y;
                    if (MODE == 0) {
                        const uint32_t win = (uint32_t)token / 49u;
                        const uint32_t nt  = (uint32_t)token - win * 49u;
                        const int head = col >> 5, d = col & 31;
                        float* dst0 = (nc == 0) ? g_q : (nc == 1) ? g_k : g_v;
                        float* dst = dst0 + ((size_t)(win * 4 + head) * 49 + nt) * 32 + d;
                        const float s = (nc == 0) ? SCALE_Q : 1.0f;
                        *reinterpret_cast<float2*>(dst) = make_float2(vx * s, vy * s);
                    } else {
                        float* dst = outp + (size_t)token * 128 + col;
                        *reinterpret_cast<float2*>(dst) = make_float2(vx, vy);
                    }
                }
            }
        }
        __syncthreads();
    }
}

// ===========================================================================
// Kernel 2: per-(window, head) attention.  8192 CTAs x 128 threads, ~29KB smem
// ===========================================================================
__global__ void __launch_bounds__(128, 6)
attn_kernel(const float* __restrict__ maskg, const float* __restrict__ relg)
{
    __shared__ float qsm[49 * 32];
    __shared__ float kT[32 * 50];
    __shared__ float vsm[49 * 32];
    __shared__ float att[49 * 50];
    __shared__ float rel[169];

    const int t = threadIdx.x;
    const int win = blockIdx.x >> 2;
    const int h = blockIdx.x & 3;
    const size_t base = ((size_t)win * 4 + h) * 1568;

    const float4* qg = reinterpret_cast<const float4*>(g_q + base);
    const float4* vg = reinterpret_cast<const float4*>(g_v + base);
    const float*  kg = g_k + base;
    #pragma unroll
    for (int it = 0; it < 4; it++) {
        int idx = t + it * 128;
        if (idx < 392) {
            reinterpret_cast<float4*>(qsm)[idx] = qg[idx];
            reinterpret_cast<float4*>(vsm)[idx] = vg[idx];
        }
    }
    #pragma unroll
    for (int it = 0; it < 13; it++) {
        int idx = t + it * 128;
        if (idx < 1568) {
            int j = idx >> 5, d = idx & 31;
            kT[d * 50 + j] = kg[idx];
        }
    }
    for (int i = t; i < 169; i += 128) rel[i] = relg[i * 4 + h];
    __syncthreads();

    const int lane = t & 31;
    const unsigned pm = 0x3u << (lane & 30);

    // ---- S = q k^T (+bias +mask), softmax.  2 threads per row i -----------
    if (t < 98) {
        const int i = t >> 1, half = t & 1;
        const int j0 = half * 24;
        const int iy = i / 7, ix = i - iy * 7;
        const float* qrow = qsm + i * 32;
        const float* mrow = maskg + ((size_t)((win & 63) * 49 + i)) * 49;

        long long acc[12];
        #pragma unroll
        for (int p = 0; p < 12; p++) acc[p] = 0;
        float acc48 = 0.f;
        #pragma unroll 4
        for (int d = 0; d < 32; d++) {
            float qd = qrow[d];
            long long qp = pk2(qd);
            const float* kr = kT + d * 50 + j0;
            #pragma unroll
            for (int p = 0; p < 12; p++)
                fma2(acc[p], qp, *reinterpret_cast<const long long*>(kr + 2 * p));
            if (half) acc48 = fmaf(qd, kT[d * 50 + 48], acc48);
        }

        float vv[25];
        float m = -3.0e38f;
        if (half == 0) {
            #pragma unroll
            for (int p = 0; p < 12; p++) {
                float2 f = up2(acc[p]);
                const int ja = 2 * p, jb = 2 * p + 1;
                float va = f.x + rel[(iy - ja / 7 + 6) * 13 + (ix - ja % 7 + 6)] + mrow[ja];
                float vb = f.y + rel[(iy - jb / 7 + 6) * 13 + (ix - jb % 7 + 6)] + mrow[jb];
                vv[2 * p] = va; vv[2 * p + 1] = vb;
                m = fmaxf(m, fmaxf(va, vb));
            }
        } else {
            #pragma unroll
            for (int p = 0; p < 12; p++) {
                float2 f = up2(acc[p]);
                const int ja = 24 + 2 * p, jb = 25 + 2 * p;
                float va = f.x + rel[(iy - ja / 7 + 6) * 13 + (ix - ja % 7 + 6)] + mrow[ja];
                float vb = f.y + rel[(iy - jb / 7 + 6) * 13 + (ix - jb % 7 + 6)] + mrow[jb];
                vv[2 * p] = va; vv[2 * p + 1] = vb;
                m = fmaxf(m, fmaxf(va, vb));
            }
            float v48 = acc48 + rel[iy * 13 + ix] + mrow[48];   // j=48: jy=jx=6
            vv[24] = v48; m = fmaxf(m, v48);
        }
        m = fmaxf(m, __shfl_xor_sync(pm, m, 1));
        float ss = 0.f;
        #pragma unroll
        for (int p = 0; p < 24; p++) { float e = __expf(vv[p] - m); vv[p] = e; ss += e; }
        if (half) { float e = __expf(vv[24] - m); vv[24] = e; ss += e; }
        ss += __shfl_xor_sync(pm, ss, 1);
        const float inv = 1.0f / ss;
        float* arow = att + i * 50 + j0;
        #pragma unroll
        for (int p = 0; p < 24; p++) arow[p] = vv[p] * inv;
        if (half) arow[24] = vv[24] * inv;
    }
    __syncthreads();

    // ---- O = P @ v.  2 threads per row i (d halves of 16) -----------------
    if (t < 98) {
        const int i = t >> 1, d0 = (t & 1) * 16;
        long long acc[8];
        #pragma unroll
        for (int p = 0; p < 8; p++) acc[p] = 0;
        const float* arow = att + i * 50;
        #pragma unroll 7
        for (int j = 0; j < 49; j++) {
            long long pp = pk2(arow[j]);
            const float* vr = vsm + j * 32 + d0;
            #pragma unroll
            for (int p = 0; p < 8; p++)
                fma2(acc[p], pp, *reinterpret_cast<const long long*>(vr + 2 * p));
        }
        float* orow = g_o + ((size_t)win * 49 + i) * 128 + h * 32 + d0;
        #pragma unroll
        for (int p = 0; p < 4; p++) {
            float2 f0 = up2(acc[2 * p]), f1 = up2(acc[2 * p + 1]);
            reinterpret_cast<float4*>(orow)[p] = make_float4(f0.x, f0.y, f1.x, f1.y);
        }
    }
}

// ===========================================================================
extern "C" void kernel_launch(void* const* d_in, const int* in_sizes, int n_in,
                              void* d_out, int out_size)
{
    const float* x      = (const float*)d_in[0];
    const float* mask   = (const float*)d_in[1];
    const float* qkv_w  = (const float*)d_in[2];
    const float* qkv_b  = (const float*)d_in[3];
    const float* proj_w = (const float*)d_in[4];
    const float* proj_b = (const float*)d_in[5];
    const float* rel    = (const float*)d_in[6];
    float* out = (float*)d_out;

    cudaFuncSetAttribute(gemm_mma_kernel<0>,
                         cudaFuncAttributeMaxDynamicSharedMemorySize, SM_GEMM_BYTES);
    cudaFuncSetAttribute(gemm_mma_kernel<1>,
                         cudaFuncAttributeMaxDynamicSharedMemorySize, SM_GEMM_BYTES);

    wprep<<<192, 256>>>(qkv_w, proj_w);
    gemm_mma_kernel<0><<<MTILES, 256, SM_GEMM_BYTES>>>(x, qkv_b, nullptr);
    attn_kernel<<<NWIN * 4, 128>>>(mask, rel);
    gemm_mma_kernel<1><<<MTILES, 256, SM_GEMM_BYTES>>>(nullptr, proj_b, out);
}